// round 14
// baseline (speedup 1.0000x reference)
#include <cuda_runtime.h>
#include <cuda_fp16.h>
#include <cuda_bf16.h>
#include <cstdint>
#include <cstddef>

#define B_  128
#define S_  512
#define I_  128
#define H_  128
#define M_  8
#define KD_ 16
#define R_  16
#define O_  128
#define MH_ 1024

#define OUT_OUTPUTS 0ull
#define OUT_HID     8388608ull
#define OUT_AIN     75497472ull
#define OUT_ACM     142606336ull
#define OUT_ATTN    209715200ull

// ---------------- scratch ----------------
__device__ float g_P[(size_t)S_ * B_ * MH_];
__device__ int   g_Pflag[S_];
__device__ float g_Wcomb[M_ * I_ * H_];
__device__ float g_biasP[MH_];
__device__ __align__(16) __nv_bfloat16 g_BinT_hi[M_ * 16384];
__device__ __align__(16) __nv_bfloat16 g_BinT_lo[M_ * 16384];
__device__ __align__(16) __nv_bfloat16 g_BpT_hi[M_ * 16384];
__device__ __align__(16) __nv_bfloat16 g_BpT_lo[M_ * 16384];
__device__ __align__(16) __nv_bfloat16 g_Wo_hi[O_ * MH_];
__device__ __align__(16) __nv_bfloat16 g_Wo_lo[O_ * MH_];

// ---------------- helpers ----------------
__device__ __forceinline__ uint32_t smem_u32(const void* p) {
    uint32_t a;
    asm("{ .reg .u64 t; cvta.to.shared.u64 t, %1; cvt.u32.u64 %0, t; }" : "=r"(a) : "l"(p));
    return a;
}
__device__ __forceinline__ uint32_t swb(int n, int k) {
    uint32_t byte = ((uint32_t)((n >> 3) + (k >> 6) * 16)) * 1024u
                  + (uint32_t)(n & 7) * 128u + (uint32_t)(k & 63) * 2u;
    return byte ^ ((byte >> 3) & 0x70u);
}
__device__ __forceinline__ void split1(float v, uint16_t& h, uint16_t& l) {
    __nv_bfloat16 bh = __float2bfloat16(v);
    float r = v - __bfloat162float(bh);
    h = __bfloat16_as_ushort(bh);
    l = __bfloat16_as_ushort(__float2bfloat16(r));
}
__device__ __forceinline__ void ldsm4(uint32_t* r, uint32_t addr) {
    asm volatile("ldmatrix.sync.aligned.m8n8.x4.shared.b16 {%0,%1,%2,%3}, [%4];"
                 : "=r"(r[0]), "=r"(r[1]), "=r"(r[2]), "=r"(r[3]) : "r"(addr));
}
__device__ __forceinline__ void mma16816(float* c, const uint32_t* a, const uint32_t* b) {
    asm volatile("mma.sync.aligned.m16n8k16.row.col.f32.bf16.bf16.f32 "
                 "{%0,%1,%2,%3}, {%4,%5,%6,%7}, {%8,%9}, {%0,%1,%2,%3};"
                 : "+f"(c[0]), "+f"(c[1]), "+f"(c[2]), "+f"(c[3])
                 : "r"(a[0]), "r"(a[1]), "r"(a[2]), "r"(a[3]), "r"(b[0]), "r"(b[1]));
}
__device__ __forceinline__ float tanhf_fast(float x) {
    float ax = fabsf(x);
    float e = __expf(-2.0f * ax);
    float r = __fdividef(1.0f - e, 1.0f + e);
    return copysignf(r, x);
}

#define A_HI 0
#define A_LO 32768
#define B_HI 65536
#define B_LO 98304
#define GEMM_SMEM 131072
#define FUSED_SMEM 131072

// ---------------------------------------------------------------------------
// prep 0: Wcomb + zero P-flags
// ---------------------------------------------------------------------------
__global__ void __launch_bounds__(256) prep_wcomb(const float* __restrict__ W_in,
                                                  const float* __restrict__ Wp) {
    extern __shared__ float s0[];
    float* Wins = s0;
    float* Wps  = s0 + 16384;
    int m = blockIdx.x, tid = threadIdx.x;
    if (m == 0) {
        for (int i = tid; i < S_; i += 256) g_Pflag[i] = 0;
    }
    const float* wi = W_in + m * 16384;
    const float* wp = Wp   + m * 16384;
    for (int i = tid; i < 16384; i += 256) {
        Wins[i] = wi[i];
        Wps[(i >> 7) * 129 + (i & 127)] = wp[i];
    }
    __syncthreads();
    for (int idx = tid; idx < 16384; idx += 256) {
        int j = idx >> 7, o = idx & 127;
        const float* a = Wins + j * 128;
        const float* b = Wps + o * 129;
        float acc = 0.f;
#pragma unroll 16
        for (int i = 0; i < 128; ++i) acc += a[i] * b[i];
        g_Wcomb[m * 16384 + idx] = acc;
    }
}

// ---------------------------------------------------------------------------
// prep 1: transpose + bf16-split weights, combine biases
// ---------------------------------------------------------------------------
__global__ void __launch_bounds__(256) prep_split(const float* __restrict__ W_in,
                                                  const float* __restrict__ Wo,
                                                  const float* __restrict__ bp,
                                                  const float* __restrict__ cbias) {
    int b = blockIdx.x, tid = threadIdx.x;
    if (b < 8) {
        int m = b;
        for (int idx = tid; idx < 16384; idx += 256) {
            int h = idx >> 7, i = idx & 127;
            uint16_t hi, lo;
            split1(W_in[m * 16384 + i * 128 + h], hi, lo);
            g_BinT_hi[m * 16384 + idx] = __ushort_as_bfloat16(hi);
            g_BinT_lo[m * 16384 + idx] = __ushort_as_bfloat16(lo);
        }
    } else if (b < 16) {
        int m = b - 8;
        for (int idx = tid; idx < 16384; idx += 256) {
            int o = idx >> 7, i = idx & 127;
            uint16_t hi, lo;
            split1(g_Wcomb[m * 16384 + i * 128 + o], hi, lo);
            g_BpT_hi[m * 16384 + idx] = __ushort_as_bfloat16(hi);
            g_BpT_lo[m * 16384 + idx] = __ushort_as_bfloat16(lo);
        }
    } else if (b < 32) {
        int s = b - 16;
        for (int idx = tid; idx < 8192; idx += 256) {
            int g = s * 8192 + idx;
            uint16_t hi, lo;
            split1(Wo[g], hi, lo);
            g_Wo_hi[g] = __ushort_as_bfloat16(hi);
            g_Wo_lo[g] = __ushort_as_bfloat16(lo);
        }
    } else {
        for (int idx = tid; idx < MH_; idx += 256) g_biasP[idx] = bp[idx] + cbias[idx];
    }
}

// ---------------------------------------------------------------------------
// device: one x-by-weights GEMM CTA (8 m-blocks), isP selects target
// ---------------------------------------------------------------------------
__device__ void gemm_xw_path(int t, bool isP, const float* __restrict__ x,
                             float* __restrict__ out, char* smc) {
    uint32_t sb = smem_u32(smc);
    int tid = threadIdx.x, w = tid >> 5, lane = tid & 31;

    {   // convert A tile (x rows) to split bf16, swizzled
        int rb = tid >> 1, half = tid & 1;
        const float4* xr = (const float4*)(x + ((size_t)rb * S_ + t) * I_ + half * 64);
#pragma unroll
        for (int q = 0; q < 16; ++q) {
            float4 v = xr[q];
            int k0 = half * 64 + q * 4;
            uint16_t h0, h1, h2, h3, l0, l1, l2, l3;
            split1(v.x, h0, l0); split1(v.y, h1, l1);
            split1(v.z, h2, l2); split1(v.w, h3, l3);
            uint2 hv = make_uint2((uint32_t)h0 | ((uint32_t)h1 << 16),
                                  (uint32_t)h2 | ((uint32_t)h3 << 16));
            uint2 lv = make_uint2((uint32_t)l0 | ((uint32_t)l1 << 16),
                                  (uint32_t)l2 | ((uint32_t)l3 << 16));
            uint32_t off = swb(rb, k0);
            *(uint2*)(smc + A_HI + off) = hv;
            *(uint2*)(smc + A_LO + off) = lv;
        }
    }

    int lq = lane >> 3, ll = lane & 7;
    int a_row = w * 16 + ll + (lq & 1) * 8;
    int a_kadd = (lq >> 1) * 8;
    int b_rc = (lq >> 1) * 8 + ll;
    int b_kadd = (lq & 1) * 8;
    int c_row = w * 16 + (lane >> 2);
    int c_col = (lane & 3) * 2;

    for (int m = 0; m < 8; ++m) {
        const __nv_bfloat16* gh = (isP ? g_BpT_hi : g_BinT_hi) + m * 16384;
        const __nv_bfloat16* gl = (isP ? g_BpT_lo : g_BinT_lo) + m * 16384;
#pragma unroll
        for (int q = 0; q < 8; ++q) {
            int u = tid + q * 256;
            int n = u >> 4, k0 = (u & 15) * 8;
            uint4 vh = ((const uint4*)gh)[u];
            uint4 vl = ((const uint4*)gl)[u];
            uint32_t off = swb(n, k0);
            *(uint4*)(smc + B_HI + off) = vh;
            *(uint4*)(smc + B_LO + off) = vl;
        }
        __syncthreads();

        float c[16][4];
#pragma unroll
        for (int i = 0; i < 16; ++i)
#pragma unroll
            for (int j = 0; j < 4; ++j) c[i][j] = 0.f;

        for (int ks = 0; ks < 8; ++ks) {
            int k0 = ks * 16;
            uint32_t ah[4], al[4];
            uint32_t aoff = swb(a_row, k0 + a_kadd);
            ldsm4(ah, sb + A_HI + aoff);
            ldsm4(al, sb + A_LO + aoff);
#pragma unroll
            for (int np = 0; np < 8; ++np) {
                uint32_t bh[4], bl[4];
                uint32_t boff = swb(np * 16 + b_rc, k0 + b_kadd);
                ldsm4(bh, sb + B_HI + boff);
                ldsm4(bl, sb + B_LO + boff);
                mma16816(c[2 * np],     ah, bh);
                mma16816(c[2 * np],     ah, bl);
                mma16816(c[2 * np],     al, bh);
                mma16816(c[2 * np + 1], ah, bh + 2);
                mma16816(c[2 * np + 1], ah, bl + 2);
                mma16816(c[2 * np + 1], al, bh + 2);
            }
        }

        if (!isP) {
            float* d0 = out + OUT_AIN + ((size_t)t * B_ + c_row) * MH_ + m * H_;
            float* d1 = out + OUT_AIN + ((size_t)t * B_ + c_row + 8) * MH_ + m * H_;
#pragma unroll
            for (int nt = 0; nt < 16; ++nt) {
                int col = nt * 8 + c_col;
                *(float2*)(d0 + col) = make_float2(c[nt][0], c[nt][1]);
                *(float2*)(d1 + col) = make_float2(c[nt][2], c[nt][3]);
            }
        } else {
            float* d0 = g_P + ((size_t)t * B_ + c_row) * MH_ + m * H_;
            float* d1 = g_P + ((size_t)t * B_ + c_row + 8) * MH_ + m * H_;
#pragma unroll
            for (int nt = 0; nt < 16; ++nt) {
                int col = nt * 8 + c_col;
                float2 bi = *(const float2*)(g_biasP + m * H_ + col);
                *(float2*)(d0 + col) = make_float2(c[nt][0] + bi.x, c[nt][1] + bi.y);
                *(float2*)(d1 + col) = make_float2(c[nt][2] + bi.x, c[nt][3] + bi.y);
            }
        }
        __syncthreads();
    }

    if (isP && tid == 0) {
        __threadfence();
        *((volatile int*)&g_Pflag[t]) = 1;
    }
}

// ---------------------------------------------------------------------------
// device: wait for P[t] published
// ---------------------------------------------------------------------------
__device__ __forceinline__ void wait_pflag(int t) {
    if (*((volatile int*)&g_Pflag[t]) == 0) {
        while (*((volatile int*)&g_Pflag[t]) == 0) __nanosleep(100);
    }
    __threadfence();
}

// ---------------------------------------------------------------------------
// FUSED kernel: blocks 0-127 seq, 128-639 P producers, 640-1151 A_in.
// seq smem: half Wt[256*136] | uint his_h[512] | float vcs[2][1024] | KQ[2][256]
// ---------------------------------------------------------------------------
#define WT_HALFS (256 * 136)

__global__ void __launch_bounds__(256) fused_kernel(const float* __restrict__ x,
                                                    const float* __restrict__ U,
                                                    const float* __restrict__ V,
                                                    const float* __restrict__ WQ,
                                                    const float* __restrict__ WK,
                                                    const float* __restrict__ WV,
                                                    float* __restrict__ out) {
    extern __shared__ char smc[];
    int bid = blockIdx.x;

    if (bid >= 128) {
        bool isP = bid < 640;
        int t = isP ? (bid - 128) : (bid - 640);
        gemm_xw_path(t, isP, x, out, smc);
        return;
    }

    // ---------------- sequential recurrence path ----------------
    __half* Wt = (__half*)smc;
    uint32_t* his_h = (uint32_t*)(Wt + WT_HALFS);
    float* vcsB = (float*)(his_h + 512);
    float* KQB = vcsB + 2048;

    int tid = threadIdx.x, b = bid;
    int w = tid >> 5, lane = tid & 31;
    int h4 = lane * 4;

    for (int i = tid; i < 16384; i += 256) {
        int m = i >> 11, h = (i >> 4) & 127, k = i & 15;
        Wt[(m * 32 + k) * 136 + h] = __float2half(WK[i]);
        Wt[(m * 32 + 16 + k) * 136 + h] = __float2half(WQ[i]);
    }

    float Ur[4][16];
#pragma unroll
    for (int j = 0; j < 4; ++j) {
        const float4* ur = (const float4*)(U + w * 2048 + (h4 + j) * 16);
#pragma unroll
        for (int q = 0; q < 4; ++q) {
            float4 v = ur[q];
            Ur[j][q * 4 + 0] = v.x; Ur[j][q * 4 + 1] = v.y;
            Ur[j][q * 4 + 2] = v.z; Ur[j][q * 4 + 3] = v.w;
        }
    }
    float4 Vr[16];
#pragma unroll
    for (int r = 0; r < 16; ++r)
        Vr[r] = *(const float4*)(V + w * 2048 + r * 128 + h4);

    float4 wv4;
    wv4.x = WV[w * 16384 + (h4 + 0) * 128 + (h4 + 0)];
    wv4.y = WV[w * 16384 + (h4 + 1) * 128 + (h4 + 1)];
    wv4.z = WV[w * 16384 + (h4 + 2) * 128 + (h4 + 2)];
    wv4.w = WV[w * 16384 + (h4 + 3) * 128 + (h4 + 3)];

    float4 s = make_float4(0.f, 0.f, 0.f, 0.f);
    __syncthreads();

    const __half* Wr = Wt + (w * 32 + lane) * 136;
    const uint4* Hm4 = (const uint4*)(his_h + w * 64);
    int md = lane >> 2, n0 = (lane & 3) * 2;

    wait_pflag(0);
    float4 p4 = *(const float4*)(g_P + (size_t)b * MH_ + w * 128 + h4);
    int par = 0;

    for (int t = 0; t < S_; ++t) {
        float* vcs = vcsB + par * 1024;
        float* Kc = KQB + par * 256;
        float* Qc = Kc + 128;

        // ---- a: partials + reduce-scatter
        float part[16];
#pragma unroll
        for (int r = 0; r < 16; ++r)
            part[r] = s.x * Ur[0][r] + s.y * Ur[1][r] + s.z * Ur[2][r] + s.w * Ur[3][r];
        {
            bool sel = (lane & 16) != 0;
#pragma unroll
            for (int j = 0; j < 8; ++j) {
                float keep = sel ? part[8 + j] : part[j];
                float send = sel ? part[j] : part[8 + j];
                part[j] = keep + __shfl_xor_sync(0xffffffffu, send, 16);
            }
        }
        {
            bool sel = (lane & 8) != 0;
#pragma unroll
            for (int j = 0; j < 4; ++j) {
                float keep = sel ? part[4 + j] : part[j];
                float send = sel ? part[j] : part[4 + j];
                part[j] = keep + __shfl_xor_sync(0xffffffffu, send, 8);
            }
        }
        {
            bool sel = (lane & 4) != 0;
#pragma unroll
            for (int j = 0; j < 2; ++j) {
                float keep = sel ? part[2 + j] : part[j];
                float send = sel ? part[j] : part[2 + j];
                part[j] = keep + __shfl_xor_sync(0xffffffffu, send, 4);
            }
        }
        {
            bool sel = (lane & 2) != 0;
            float keep = sel ? part[1] : part[0];
            float send = sel ? part[0] : part[1];
            part[0] = keep + __shfl_xor_sync(0xffffffffu, send, 2);
        }
        float tsum = part[0] + __shfl_xor_sync(0xffffffffu, part[0], 1);

        // ---- b
        float4 hin;
        {
            float4 z = p4;
#pragma unroll
            for (int r = 0; r < 16; ++r) {
                float tr = __shfl_sync(0xffffffffu, tsum, r << 1);
                z.x += tr * Vr[r].x; z.y += tr * Vr[r].y;
                z.z += tr * Vr[r].z; z.w += tr * Vr[r].w;
            }
            hin.x = tanhf_fast(z.x); hin.y = tanhf_fast(z.y);
            hin.z = tanhf_fast(z.z); hin.w = tanhf_fast(z.w);
            __half2 p01 = __floats2half2_rn(hin.x, hin.y);
            __half2 p23 = __floats2half2_rn(hin.z, hin.w);
            *(uint2*)(his_h + w * 64 + lane * 2) =
                make_uint2(*(uint32_t*)&p01, *(uint32_t*)&p23);
            *(float4*)(vcs + w * 128 + h4) = make_float4(hin.x * wv4.x, hin.y * wv4.y,
                                                         hin.z * wv4.z, hin.w * wv4.w);
        }
        __syncwarp();

        // ---- c (half2)
        {
            __half2 a0 = __float2half2_rn(0.f), a1 = a0, a2 = a0, a3 = a0;
#pragma unroll
            for (int j = 0; j < 16; ++j) {
                uint4 w8 = *(const uint4*)(Wr + j * 8);
                uint4 h8 = Hm4[j];
                a0 = __hfma2(*(__half2*)&w8.x, *(__half2*)&h8.x, a0);
                a1 = __hfma2(*(__half2*)&w8.y, *(__half2*)&h8.y, a1);
                a2 = __hfma2(*(__half2*)&w8.z, *(__half2*)&h8.z, a2);
                a3 = __hfma2(*(__half2*)&w8.w, *(__half2*)&h8.w, a3);
            }
            __half2 s01 = __hadd2(a0, a1);
            __half2 s23 = __hadd2(a2, a3);
            __half2 ss = __hadd2(s01, s23);
            float acc = __half2float(__low2half(ss)) + __half2float(__high2half(ss));
            float* Xc = (lane < 16) ? Kc : Qc;
            Xc[w * 16 + (lane & 15)] = acc;
        }
        __syncthreads();   // the ONLY block barrier

        // ---- prefetch next P (flag-gated)
        float4 pn;
        {
            int tn = (t + 1) & (S_ - 1);
            if (t + 1 < S_) wait_pflag(tn);
            pn = *(const float4*)(g_P + ((size_t)tn * B_ + b) * MH_ + w * 128 + h4);
        }

        // ---- d
        float a0f, a1f;
        {
            const float* qrow = Qc + md * 16;
            const float* k0r = Kc + n0 * 16;
            const float* k1r = k0r + 16;
            float lg0 = 0.f, lg1 = 0.f;
#pragma unroll
            for (int k4 = 0; k4 < 16; k4 += 4) {
                float4 q = *(const float4*)(qrow + k4);
                float4 ka = *(const float4*)(k0r + k4);
                float4 kb = *(const float4*)(k1r + k4);
                lg0 += q.x * ka.x + q.y * ka.y + q.z * ka.z + q.w * ka.w;
                lg1 += q.x * kb.x + q.y * kb.y + q.z * kb.z + q.w * kb.w;
            }
            lg0 *= 0.25f; lg1 *= 0.25f;
            float mx = fmaxf(lg0, lg1);
            mx = fmaxf(mx, __shfl_xor_sync(0xffffffffu, mx, 1));
            mx = fmaxf(mx, __shfl_xor_sync(0xffffffffu, mx, 2));
            float e0 = __expf(lg0 - mx), e1 = __expf(lg1 - mx);
            float sm2 = e0 + e1;
            sm2 += __shfl_xor_sync(0xffffffffu, sm2, 1);
            sm2 += __shfl_xor_sync(0xffffffffu, sm2, 2);
            float inv = __fdividef(1.0f, sm2);
            a0f = e0 * inv; a1f = e1 * inv;
            if (w == 0)
                *(float2*)(out + OUT_ATTN + ((size_t)t * B_ + b) * 64 + md * 8 + n0)
                    = make_float2(a0f, a1f);
        }

        // ---- e
        {
            float sel = (w & 1) ? a1f : a0f;
            int srcq = w >> 1;
            float4 ac = make_float4(0.f, 0.f, 0.f, 0.f);
#pragma unroll
            for (int mm = 0; mm < 8; ++mm) {
                float av = __shfl_sync(0xffffffffu, sel, mm * 4 + srcq);
                float4 v = *(const float4*)(vcs + mm * 128 + h4);
                ac.x += av * v.x; ac.y += av * v.y;
                ac.z += av * v.z; ac.w += av * v.w;
            }
            float4 hnew = make_float4(hin.x + ac.x, hin.y + ac.y,
                                      hin.z + ac.z, hin.w + ac.w);
            size_t gbase = ((size_t)t * B_ + b) * MH_ + w * 128 + h4;
            *(float4*)(out + OUT_ACM + gbase) = ac;
            *(float4*)(out + OUT_HID + gbase) = hnew;
            s = hnew;
        }
        p4 = pn;
        par ^= 1;
    }
}

// ---------------------------------------------------------------------------
// GEMM C (mma.sync bf16-split) — unchanged
// ---------------------------------------------------------------------------
__global__ void __launch_bounds__(256)
gemm_out_mma(const float* __restrict__ bo, float* __restrict__ out) {
    extern __shared__ char smc[];
    uint32_t sb = smem_u32(smc);
    int tid = threadIdx.x, w = tid >> 5, lane = tid & 31, t = blockIdx.x;
    const float* hid = out + OUT_HID + (size_t)t * B_ * MH_;

    int lq = lane >> 3, ll = lane & 7;
    int a_row = w * 16 + ll + (lq & 1) * 8;
    int a_kadd = (lq >> 1) * 8;
    int b_rc = (lq >> 1) * 8 + ll;
    int b_kadd = (lq & 1) * 8;
    int c_row = w * 16 + (lane >> 2);
    int c_col = (lane & 3) * 2;

    float c[16][4];
#pragma unroll
    for (int i = 0; i < 16; ++i)
#pragma unroll
        for (int j = 0; j < 4; ++j) c[i][j] = 0.f;

    for (int kc = 0; kc < 8; ++kc) {
        {
            int rb = tid >> 1, half = tid & 1;
            const float4* ar = (const float4*)(hid + (size_t)rb * MH_ + kc * 128 + half * 64);
#pragma unroll
            for (int q = 0; q < 16; ++q) {
                float4 v = ar[q];
                int k0 = half * 64 + q * 4;
                uint16_t h0, h1, h2, h3, l0, l1, l2, l3;
                split1(v.x, h0, l0); split1(v.y, h1, l1);
                split1(v.z, h2, l2); split1(v.w, h3, l3);
                uint2 hv = make_uint2((uint32_t)h0 | ((uint32_t)h1 << 16),
                                      (uint32_t)h2 | ((uint32_t)h3 << 16));
                uint2 lv = make_uint2((uint32_t)l0 | ((uint32_t)l1 << 16),
                                      (uint32_t)l2 | ((uint32_t)l3 << 16));
                uint32_t off = swb(rb, k0);
                *(uint2*)(smc + A_HI + off) = hv;
                *(uint2*)(smc + A_LO + off) = lv;
            }
        }
#pragma unroll
        for (int q = 0; q < 8; ++q) {
            int u = tid + q * 256;
            int n = u >> 4, k0 = (u & 15) * 8;
            uint4 vh = *(const uint4*)(g_Wo_hi + (size_t)n * MH_ + kc * 128 + k0);
            uint4 vl = *(const uint4*)(g_Wo_lo + (size_t)n * MH_ + kc * 128 + k0);
            uint32_t off = swb(n, k0);
            *(uint4*)(smc + B_HI + off) = vh;
            *(uint4*)(smc + B_LO + off) = vl;
        }
        __syncthreads();

        for (int ks = 0; ks < 8; ++ks) {
            int k0 = ks * 16;
            uint32_t ah[4], al[4];
            uint32_t aoff = swb(a_row, k0 + a_kadd);
            ldsm4(ah, sb + A_HI + aoff);
            ldsm4(al, sb + A_LO + aoff);
#pragma unroll
            for (int np = 0; np < 8; ++np) {
                uint32_t bh[4], bl[4];
                uint32_t boff = swb(np * 16 + b_rc, k0 + b_kadd);
                ldsm4(bh, sb + B_HI + boff);
                ldsm4(bl, sb + B_LO + boff);
                mma16816(c[2 * np],     ah, bh);
                mma16816(c[2 * np],     ah, bl);
                mma16816(c[2 * np],     al, bh);
                mma16816(c[2 * np + 1], ah, bh + 2);
                mma16816(c[2 * np + 1], ah, bl + 2);
                mma16816(c[2 * np + 1], al, bh + 2);
            }
        }
        __syncthreads();
    }

    float* d0 = out + OUT_OUTPUTS + ((size_t)c_row * S_ + t) * O_;
    float* d1 = out + OUT_OUTPUTS + ((size_t)(c_row + 8) * S_ + t) * O_;
#pragma unroll
    for (int nt = 0; nt < 16; ++nt) {
        int col = nt * 8 + c_col;
        float2 bi = *(const float2*)(bo + col);
        *(float2*)(d0 + col) = make_float2(c[nt][0] + bi.x, c[nt][1] + bi.y);
        *(float2*)(d1 + col) = make_float2(c[nt][2] + bi.x, c[nt][3] + bi.y);
    }
}

extern "C" void kernel_launch(void* const* d_in, const int* in_sizes, int n_in,
                              void* d_out, int out_size) {
    const float* x     = (const float*)d_in[0];
    const float* Wp    = (const float*)d_in[1];
    const float* bp    = (const float*)d_in[2];
    const float* U     = (const float*)d_in[3];
    const float* V     = (const float*)d_in[4];
    const float* cbias = (const float*)d_in[5];
    const float* W_in  = (const float*)d_in[6];
    const float* W_Q   = (const float*)d_in[7];
    const float* W_K   = (const float*)d_in[8];
    const float* W_V   = (const float*)d_in[9];
    const float* Wo    = (const float*)d_in[10];
    const float* bo    = (const float*)d_in[11];
    float* out = (float*)d_out;

    static bool attr_done = false;
    if (!attr_done) {
        cudaFuncSetAttribute(prep_wcomb,   cudaFuncAttributeMaxDynamicSharedMemorySize, 132608);
        cudaFuncSetAttribute(fused_kernel, cudaFuncAttributeMaxDynamicSharedMemorySize, FUSED_SMEM);
        cudaFuncSetAttribute(gemm_out_mma, cudaFuncAttributeMaxDynamicSharedMemorySize, GEMM_SMEM);
        attr_done = true;
    }

    prep_wcomb<<<M_, 256, 132608>>>(W_in, Wp);
    prep_split<<<33, 256>>>(W_in, Wo, bp, cbias);
    fused_kernel<<<128 + 2 * S_, 256, FUSED_SMEM>>>(x, U, V, W_Q, W_K, W_V, out);
    gemm_out_mma<<<S_, 256, GEMM_SMEM>>>(bo, out);
}

// round 15
// speedup vs baseline: 1.1261x; 1.1261x over previous
#include <cuda_runtime.h>
#include <cuda_fp16.h>
#include <cuda_bf16.h>
#include <cstdint>
#include <cstddef>

#define B_  128
#define S_  512
#define I_  128
#define H_  128
#define M_  8
#define KD_ 16
#define R_  16
#define O_  128
#define MH_ 1024

#define OUT_OUTPUTS 0ull
#define OUT_HID     8388608ull
#define OUT_AIN     75497472ull
#define OUT_ACM     142606336ull
#define OUT_ATTN    209715200ull

// ---------------- scratch ----------------
__device__ float g_P[(size_t)S_ * B_ * MH_];
__device__ float g_Wcomb[M_ * I_ * H_];
__device__ float g_biasP[MH_];
__device__ __align__(16) __nv_bfloat16 g_BinT_hi[M_ * 16384];
__device__ __align__(16) __nv_bfloat16 g_BinT_lo[M_ * 16384];
__device__ __align__(16) __nv_bfloat16 g_BpT_hi[M_ * 16384];
__device__ __align__(16) __nv_bfloat16 g_BpT_lo[M_ * 16384];
__device__ __align__(16) __nv_bfloat16 g_Wo_hi[O_ * MH_];
__device__ __align__(16) __nv_bfloat16 g_Wo_lo[O_ * MH_];

// ---------------- helpers ----------------
__device__ __forceinline__ uint32_t smem_u32(const void* p) {
    uint32_t a;
    asm("{ .reg .u64 t; cvta.to.shared.u64 t, %1; cvt.u32.u64 %0, t; }" : "=r"(a) : "l"(p));
    return a;
}
// 128-row bf16 tile swizzle (16 atom-rows x 2 atom-cols)
__device__ __forceinline__ uint32_t swb(int n, int k) {
    uint32_t byte = ((uint32_t)((n >> 3) + (k >> 6) * 16)) * 1024u
                  + (uint32_t)(n & 7) * 128u + (uint32_t)(k & 63) * 2u;
    return byte ^ ((byte >> 3) & 0x70u);
}
// 64-row bf16 tile swizzle (8 atom-rows x 2 atom-cols)
__device__ __forceinline__ uint32_t swb64(int n, int k) {
    uint32_t byte = ((uint32_t)((n >> 3) + (k >> 6) * 8)) * 1024u
                  + (uint32_t)(n & 7) * 128u + (uint32_t)(k & 63) * 2u;
    return byte ^ ((byte >> 3) & 0x70u);
}
__device__ __forceinline__ void split1(float v, uint16_t& h, uint16_t& l) {
    __nv_bfloat16 bh = __float2bfloat16(v);
    float r = v - __bfloat162float(bh);
    h = __bfloat16_as_ushort(bh);
    l = __bfloat16_as_ushort(__float2bfloat16(r));
}
__device__ __forceinline__ void ldsm4(uint32_t* r, uint32_t addr) {
    asm volatile("ldmatrix.sync.aligned.m8n8.x4.shared.b16 {%0,%1,%2,%3}, [%4];"
                 : "=r"(r[0]), "=r"(r[1]), "=r"(r[2]), "=r"(r[3]) : "r"(addr));
}
__device__ __forceinline__ void mma16816(float* c, const uint32_t* a, const uint32_t* b) {
    asm volatile("mma.sync.aligned.m16n8k16.row.col.f32.bf16.bf16.f32 "
                 "{%0,%1,%2,%3}, {%4,%5,%6,%7}, {%8,%9}, {%0,%1,%2,%3};"
                 : "+f"(c[0]), "+f"(c[1]), "+f"(c[2]), "+f"(c[3])
                 : "r"(a[0]), "r"(a[1]), "r"(a[2]), "r"(a[3]), "r"(b[0]), "r"(b[1]));
}
__device__ __forceinline__ float tanhf_fast(float x) {
    float ax = fabsf(x);
    float e = __expf(-2.0f * ax);
    float r = __fdividef(1.0f - e, 1.0f + e);
    return copysignf(r, x);
}

// batch-split gemm smem layout: A 2x16KB, B 2x32KB = 96KB
#define A_HI 0
#define A_LO 16384
#define B_HI 32768
#define B_LO 65536
#define GEMM_SMEM 98304

// ---------------------------------------------------------------------------
// prep 0: Wcomb[m,i,o] = sum_h W_in[m,i,h] * Wp[m,o,h]
// ---------------------------------------------------------------------------
__global__ void __launch_bounds__(256) prep_wcomb(const float* __restrict__ W_in,
                                                  const float* __restrict__ Wp) {
    extern __shared__ float s0[];
    float* Wins = s0;
    float* Wps  = s0 + 16384;   // stride 129
    int m = blockIdx.x, tid = threadIdx.x;
    const float* wi = W_in + m * 16384;
    const float* wp = Wp   + m * 16384;
    for (int i = tid; i < 16384; i += 256) {
        Wins[i] = wi[i];
        Wps[(i >> 7) * 129 + (i & 127)] = wp[i];
    }
    __syncthreads();
    for (int idx = tid; idx < 16384; idx += 256) {
        int j = idx >> 7, o = idx & 127;
        const float* a = Wins + j * 128;
        const float* b = Wps + o * 129;
        float acc = 0.f;
#pragma unroll 16
        for (int i = 0; i < 128; ++i) acc += a[i] * b[i];
        g_Wcomb[m * 16384 + idx] = acc;
    }
}

// ---------------------------------------------------------------------------
// prep 1: transpose + bf16-split weights, combine biases
// ---------------------------------------------------------------------------
__global__ void __launch_bounds__(256) prep_split(const float* __restrict__ W_in,
                                                  const float* __restrict__ Wo,
                                                  const float* __restrict__ bp,
                                                  const float* __restrict__ cbias) {
    int b = blockIdx.x, tid = threadIdx.x;
    if (b < 8) {
        int m = b;
        for (int idx = tid; idx < 16384; idx += 256) {
            int h = idx >> 7, i = idx & 127;
            uint16_t hi, lo;
            split1(W_in[m * 16384 + i * 128 + h], hi, lo);
            g_BinT_hi[m * 16384 + idx] = __ushort_as_bfloat16(hi);
            g_BinT_lo[m * 16384 + idx] = __ushort_as_bfloat16(lo);
        }
    } else if (b < 16) {
        int m = b - 8;
        for (int idx = tid; idx < 16384; idx += 256) {
            int o = idx >> 7, i = idx & 127;
            uint16_t hi, lo;
            split1(g_Wcomb[m * 16384 + i * 128 + o], hi, lo);
            g_BpT_hi[m * 16384 + idx] = __ushort_as_bfloat16(hi);
            g_BpT_lo[m * 16384 + idx] = __ushort_as_bfloat16(lo);
        }
    } else if (b < 32) {
        int s = b - 16;
        for (int idx = tid; idx < 8192; idx += 256) {
            int g = s * 8192 + idx;
            uint16_t hi, lo;
            split1(Wo[g], hi, lo);
            g_Wo_hi[g] = __ushort_as_bfloat16(hi);
            g_Wo_lo[g] = __ushort_as_bfloat16(lo);
        }
    } else {
        for (int idx = tid; idx < MH_; idx += 256) g_biasP[idx] = bp[idx] + cbias[idx];
    }
}

// ---------------------------------------------------------------------------
// GEMM A (mma.sync bf16-split), batch-split: CTA handles 64 batch rows.
// grid = (2, S_).  16 weight blocks (8 A_in + 8 P).
// ---------------------------------------------------------------------------
__global__ void __launch_bounds__(256)
gemm_in_mma(const float* __restrict__ x, float* __restrict__ out) {
    extern __shared__ char smc[];
    uint32_t sb = smem_u32(smc);
    int tid = threadIdx.x, w = tid >> 5, lane = tid & 31;
    int t = blockIdx.y, half = blockIdx.x;

    {   // convert A tile (64 x rows) to split bf16, swizzled
        int rb = tid >> 2, qq = (tid & 3) * 32;
        const float4* xr = (const float4*)(x + ((size_t)(half * 64 + rb) * S_ + t) * I_ + qq);
#pragma unroll
        for (int q = 0; q < 8; ++q) {
            float4 v = xr[q];
            int k0 = qq + q * 4;
            uint16_t h0, h1, h2, h3, l0, l1, l2, l3;
            split1(v.x, h0, l0); split1(v.y, h1, l1);
            split1(v.z, h2, l2); split1(v.w, h3, l3);
            uint2 hv = make_uint2((uint32_t)h0 | ((uint32_t)h1 << 16),
                                  (uint32_t)h2 | ((uint32_t)h3 << 16));
            uint2 lv = make_uint2((uint32_t)l0 | ((uint32_t)l1 << 16),
                                  (uint32_t)l2 | ((uint32_t)l3 << 16));
            uint32_t off = swb64(rb, k0);
            *(uint2*)(smc + A_HI + off) = hv;
            *(uint2*)(smc + A_LO + off) = lv;
        }
    }

    int lq = lane >> 3, ll = lane & 7;
    int rt = w >> 1, ch = w & 1;
    int a_row = rt * 16 + ll + (lq & 1) * 8;
    int a_kadd = (lq >> 1) * 8;
    int b_rc = (lq >> 1) * 8 + ll;
    int b_kadd = (lq & 1) * 8;
    int c_row = rt * 16 + (lane >> 2);
    int c_col = (lane & 3) * 2;

    for (int blk = 0; blk < 16; ++blk) {
        int m = blk & 7;
        bool isP = blk >= 8;
        const __nv_bfloat16* gh = (isP ? g_BpT_hi : g_BinT_hi) + m * 16384;
        const __nv_bfloat16* gl = (isP ? g_BpT_lo : g_BinT_lo) + m * 16384;
#pragma unroll
        for (int q = 0; q < 8; ++q) {
            int u = tid + q * 256;
            int n = u >> 4, k0 = (u & 15) * 8;
            uint4 vh = ((const uint4*)gh)[u];
            uint4 vl = ((const uint4*)gl)[u];
            uint32_t off = swb(n, k0);
            *(uint4*)(smc + B_HI + off) = vh;
            *(uint4*)(smc + B_LO + off) = vl;
        }
        __syncthreads();

        float c[8][4];
#pragma unroll
        for (int i = 0; i < 8; ++i)
#pragma unroll
            for (int j = 0; j < 4; ++j) c[i][j] = 0.f;

        for (int ks = 0; ks < 8; ++ks) {
            int k0 = ks * 16;
            uint32_t ah[4], al[4];
            uint32_t aoff = swb64(a_row, k0 + a_kadd);
            ldsm4(ah, sb + A_HI + aoff);
            ldsm4(al, sb + A_LO + aoff);
#pragma unroll
            for (int np = 0; np < 4; ++np) {
                uint32_t bh[4], bl[4];
                uint32_t boff = swb(ch * 64 + np * 16 + b_rc, k0 + b_kadd);
                ldsm4(bh, sb + B_HI + boff);
                ldsm4(bl, sb + B_LO + boff);
                mma16816(c[2 * np],     ah, bh);
                mma16816(c[2 * np],     ah, bl);
                mma16816(c[2 * np],     al, bh);
                mma16816(c[2 * np + 1], ah, bh + 2);
                mma16816(c[2 * np + 1], ah, bl + 2);
                mma16816(c[2 * np + 1], al, bh + 2);
            }
        }

        int r0 = half * 64 + c_row;
        if (!isP) {
            float* d0 = out + OUT_AIN + ((size_t)t * B_ + r0) * MH_ + m * H_ + ch * 64;
            float* d1 = out + OUT_AIN + ((size_t)t * B_ + r0 + 8) * MH_ + m * H_ + ch * 64;
#pragma unroll
            for (int nt = 0; nt < 8; ++nt) {
                int col = nt * 8 + c_col;
                *(float2*)(d0 + col) = make_float2(c[nt][0], c[nt][1]);
                *(float2*)(d1 + col) = make_float2(c[nt][2], c[nt][3]);
            }
        } else {
            float* d0 = g_P + ((size_t)t * B_ + r0) * MH_ + m * H_ + ch * 64;
            float* d1 = g_P + ((size_t)t * B_ + r0 + 8) * MH_ + m * H_ + ch * 64;
#pragma unroll
            for (int nt = 0; nt < 8; ++nt) {
                int col = nt * 8 + c_col;
                float2 bi = *(const float2*)(g_biasP + m * H_ + ch * 64 + col);
                *(float2*)(d0 + col) = make_float2(c[nt][0] + bi.x, c[nt][1] + bi.y);
                *(float2*)(d1 + col) = make_float2(c[nt][2] + bi.x, c[nt][3] + bi.y);
            }
        }
        __syncthreads();
    }
}

// ---------------------------------------------------------------------------
// GEMM C (mma.sync bf16-split), batch-split: CTA handles 64 batch rows.
// grid = (2, S_). K=1024 in 8 chunks, C persistent in registers.
// ---------------------------------------------------------------------------
__global__ void __launch_bounds__(256)
gemm_out_mma(const float* __restrict__ bo, float* __restrict__ out) {
    extern __shared__ char smc[];
    uint32_t sb = smem_u32(smc);
    int tid = threadIdx.x, w = tid >> 5, lane = tid & 31;
    int t = blockIdx.y, half = blockIdx.x;
    const float* hid = out + OUT_HID + (size_t)t * B_ * MH_ + (size_t)half * 64 * MH_;

    int lq = lane >> 3, ll = lane & 7;
    int rt = w >> 1, ch = w & 1;
    int a_row = rt * 16 + ll + (lq & 1) * 8;
    int a_kadd = (lq >> 1) * 8;
    int b_rc = (lq >> 1) * 8 + ll;
    int b_kadd = (lq & 1) * 8;
    int c_row = rt * 16 + (lane >> 2);
    int c_col = (lane & 3) * 2;

    float c[8][4];
#pragma unroll
    for (int i = 0; i < 8; ++i)
#pragma unroll
        for (int j = 0; j < 4; ++j) c[i][j] = 0.f;

    for (int kc = 0; kc < 8; ++kc) {
        {   // A chunk: 64 hidden rows, cols kc*128..+128
            int rb = tid >> 2, qq = (tid & 3) * 32;
            const float4* ar = (const float4*)(hid + (size_t)rb * MH_ + kc * 128 + qq);
#pragma unroll
            for (int q = 0; q < 8; ++q) {
                float4 v = ar[q];
                int k0 = qq + q * 4;
                uint16_t h0, h1, h2, h3, l0, l1, l2, l3;
                split1(v.x, h0, l0); split1(v.y, h1, l1);
                split1(v.z, h2, l2); split1(v.w, h3, l3);
                uint2 hv = make_uint2((uint32_t)h0 | ((uint32_t)h1 << 16),
                                      (uint32_t)h2 | ((uint32_t)h3 << 16));
                uint2 lv = make_uint2((uint32_t)l0 | ((uint32_t)l1 << 16),
                                      (uint32_t)l2 | ((uint32_t)l3 << 16));
                uint32_t off = swb64(rb, k0);
                *(uint2*)(smc + A_HI + off) = hv;
                *(uint2*)(smc + A_LO + off) = lv;
            }
        }
#pragma unroll
        for (int q = 0; q < 8; ++q) {   // B chunk: Wo rows n, cols kc*128..+128
            int u = tid + q * 256;
            int n = u >> 4, k0 = (u & 15) * 8;
            uint4 vh = *(const uint4*)(g_Wo_hi + (size_t)n * MH_ + kc * 128 + k0);
            uint4 vl = *(const uint4*)(g_Wo_lo + (size_t)n * MH_ + kc * 128 + k0);
            uint32_t off = swb(n, k0);
            *(uint4*)(smc + B_HI + off) = vh;
            *(uint4*)(smc + B_LO + off) = vl;
        }
        __syncthreads();

        for (int ks = 0; ks < 8; ++ks) {
            int k0 = ks * 16;
            uint32_t ah[4], al[4];
            uint32_t aoff = swb64(a_row, k0 + a_kadd);
            ldsm4(ah, sb + A_HI + aoff);
            ldsm4(al, sb + A_LO + aoff);
#pragma unroll
            for (int np = 0; np < 4; ++np) {
                uint32_t bh[4], bl[4];
                uint32_t boff = swb(ch * 64 + np * 16 + b_rc, k0 + b_kadd);
                ldsm4(bh, sb + B_HI + boff);
                ldsm4(bl, sb + B_LO + boff);
                mma16816(c[2 * np],     ah, bh);
                mma16816(c[2 * np],     ah, bl);
                mma16816(c[2 * np],     al, bh);
                mma16816(c[2 * np + 1], ah, bh + 2);
                mma16816(c[2 * np + 1], ah, bl + 2);
                mma16816(c[2 * np + 1], al, bh + 2);
            }
        }
        __syncthreads();
    }

    int r0 = half * 64 + c_row;
    float* d0 = out + OUT_OUTPUTS + ((size_t)r0 * S_ + t) * O_ + ch * 64;
    float* d1 = out + OUT_OUTPUTS + ((size_t)(r0 + 8) * S_ + t) * O_ + ch * 64;
#pragma unroll
    for (int nt = 0; nt < 8; ++nt) {
        int col = nt * 8 + c_col;
        float2 bi = *(const float2*)(bo + ch * 64 + col);
        *(float2*)(d0 + col) = make_float2(c[nt][0] + bi.x, c[nt][1] + bi.y);
        *(float2*)(d1 + col) = make_float2(c[nt][2] + bi.x, c[nt][3] + bi.y);
    }
}

// ---------------------------------------------------------------------------
// Kernel B: sequential recurrence — unchanged from R13 (passing, 966us)
// ---------------------------------------------------------------------------
#define WT_HALFS (256 * 136)
#define SEQ_SMEM (WT_HALFS * 2 + 512 * 4 + (2048 + 512) * 4)

__global__ void __launch_bounds__(256) rim_seq_kernel(const float* __restrict__ U,
                                                      const float* __restrict__ V,
                                                      const float* __restrict__ WQ,
                                                      const float* __restrict__ WK,
                                                      const float* __restrict__ WV,
                                                      float* __restrict__ out) {
    extern __shared__ char smc[];
    __half* Wt = (__half*)smc;
    uint32_t* his_h = (uint32_t*)(Wt + WT_HALFS);
    float* vcsB = (float*)(his_h + 512);
    float* KQB = vcsB + 2048;

    int tid = threadIdx.x, b = blockIdx.x;
    int w = tid >> 5, lane = tid & 31;
    int h4 = lane * 4;

    for (int i = tid; i < 16384; i += 256) {
        int m = i >> 11, h = (i >> 4) & 127, k = i & 15;
        Wt[(m * 32 + k) * 136 + h] = __float2half(WK[i]);
        Wt[(m * 32 + 16 + k) * 136 + h] = __float2half(WQ[i]);
    }

    float Ur[4][16];
#pragma unroll
    for (int j = 0; j < 4; ++j) {
        const float4* ur = (const float4*)(U + w * 2048 + (h4 + j) * 16);
#pragma unroll
        for (int q = 0; q < 4; ++q) {
            float4 v = ur[q];
            Ur[j][q * 4 + 0] = v.x; Ur[j][q * 4 + 1] = v.y;
            Ur[j][q * 4 + 2] = v.z; Ur[j][q * 4 + 3] = v.w;
        }
    }
    float4 Vr[16];
#pragma unroll
    for (int r = 0; r < 16; ++r)
        Vr[r] = *(const float4*)(V + w * 2048 + r * 128 + h4);

    float4 wv4;
    wv4.x = WV[w * 16384 + (h4 + 0) * 128 + (h4 + 0)];
    wv4.y = WV[w * 16384 + (h4 + 1) * 128 + (h4 + 1)];
    wv4.z = WV[w * 16384 + (h4 + 2) * 128 + (h4 + 2)];
    wv4.w = WV[w * 16384 + (h4 + 3) * 128 + (h4 + 3)];

    float4 s = make_float4(0.f, 0.f, 0.f, 0.f);
    __syncthreads();

    const __half* Wr = Wt + (w * 32 + lane) * 136;
    const uint4* Hm4 = (const uint4*)(his_h + w * 64);
    int md = lane >> 2, n0 = (lane & 3) * 2;

    float4 p4 = *(const float4*)(g_P + (size_t)b * MH_ + w * 128 + h4);
    int par = 0;

    for (int t = 0; t < S_; ++t) {
        float* vcs = vcsB + par * 1024;
        float* Kc = KQB + par * 256;
        float* Qc = Kc + 128;

        float part[16];
#pragma unroll
        for (int r = 0; r < 16; ++r)
            part[r] = s.x * Ur[0][r] + s.y * Ur[1][r] + s.z * Ur[2][r] + s.w * Ur[3][r];
        {
            bool sel = (lane & 16) != 0;
#pragma unroll
            for (int j = 0; j < 8; ++j) {
                float keep = sel ? part[8 + j] : part[j];
                float send = sel ? part[j] : part[8 + j];
                part[j] = keep + __shfl_xor_sync(0xffffffffu, send, 16);
            }
        }
        {
            bool sel = (lane & 8) != 0;
#pragma unroll
            for (int j = 0; j < 4; ++j) {
                float keep = sel ? part[4 + j] : part[j];
                float send = sel ? part[j] : part[4 + j];
                part[j] = keep + __shfl_xor_sync(0xffffffffu, send, 8);
            }
        }
        {
            bool sel = (lane & 4) != 0;
#pragma unroll
            for (int j = 0; j < 2; ++j) {
                float keep = sel ? part[2 + j] : part[j];
                float send = sel ? part[j] : part[2 + j];
                part[j] = keep + __shfl_xor_sync(0xffffffffu, send, 4);
            }
        }
        {
            bool sel = (lane & 2) != 0;
            float keep = sel ? part[1] : part[0];
            float send = sel ? part[0] : part[1];
            part[0] = keep + __shfl_xor_sync(0xffffffffu, send, 2);
        }
        float tsum = part[0] + __shfl_xor_sync(0xffffffffu, part[0], 1);

        float4 hin;
        {
            float4 z = p4;
#pragma unroll
            for (int r = 0; r < 16; ++r) {
                float tr = __shfl_sync(0xffffffffu, tsum, r << 1);
                z.x += tr * Vr[r].x; z.y += tr * Vr[r].y;
                z.z += tr * Vr[r].z; z.w += tr * Vr[r].w;
            }
            hin.x = tanhf_fast(z.x); hin.y = tanhf_fast(z.y);
            hin.z = tanhf_fast(z.z); hin.w = tanhf_fast(z.w);
            __half2 p01 = __floats2half2_rn(hin.x, hin.y);
            __half2 p23 = __floats2half2_rn(hin.z, hin.w);
            *(uint2*)(his_h + w * 64 + lane * 2) =
                make_uint2(*(uint32_t*)&p01, *(uint32_t*)&p23);
            *(float4*)(vcs + w * 128 + h4) = make_float4(hin.x * wv4.x, hin.y * wv4.y,
                                                         hin.z * wv4.z, hin.w * wv4.w);
        }
        __syncwarp();

        {
            __half2 a0 = __float2half2_rn(0.f), a1 = a0, a2 = a0, a3 = a0;
#pragma unroll
            for (int j = 0; j < 16; ++j) {
                uint4 w8 = *(const uint4*)(Wr + j * 8);
                uint4 h8 = Hm4[j];
                a0 = __hfma2(*(__half2*)&w8.x, *(__half2*)&h8.x, a0);
                a1 = __hfma2(*(__half2*)&w8.y, *(__half2*)&h8.y, a1);
                a2 = __hfma2(*(__half2*)&w8.z, *(__half2*)&h8.z, a2);
                a3 = __hfma2(*(__half2*)&w8.w, *(__half2*)&h8.w, a3);
            }
            __half2 s01 = __hadd2(a0, a1);
            __half2 s23 = __hadd2(a2, a3);
            __half2 ss = __hadd2(s01, s23);
            float acc = __half2float(__low2half(ss)) + __half2float(__high2half(ss));
            float* Xc = (lane < 16) ? Kc : Qc;
            Xc[w * 16 + (lane & 15)] = acc;
        }
        __syncthreads();

        float4 pn;
        {
            int tn = (t + 1) & (S_ - 1);
            pn = *(const float4*)(g_P + ((size_t)tn * B_ + b) * MH_ + w * 128 + h4);
        }

        float a0f, a1f;
        {
            const float* qrow = Qc + md * 16;
            const float* k0r = Kc + n0 * 16;
            const float* k1r = k0r + 16;
            float lg0 = 0.f, lg1 = 0.f;
#pragma unroll
            for (int k4 = 0; k4 < 16; k4 += 4) {
                float4 q = *(const float4*)(qrow + k4);
                float4 ka = *(const float4*)(k0r + k4);
                float4 kb = *(const float4*)(k1r + k4);
                lg0 += q.x * ka.x + q.y * ka.y + q.z * ka.z + q.w * ka.w;
                lg1 += q.x * kb.x + q.y * kb.y + q.z * kb.z + q.w * kb.w;
            }
            lg0 *= 0.25f; lg1 *= 0.25f;
            float mx = fmaxf(lg0, lg1);
            mx = fmaxf(mx, __shfl_xor_sync(0xffffffffu, mx, 1));
            mx = fmaxf(mx, __shfl_xor_sync(0xffffffffu, mx, 2));
            float e0 = __expf(lg0 - mx), e1 = __expf(lg1 - mx);
            float sm2 = e0 + e1;
            sm2 += __shfl_xor_sync(0xffffffffu, sm2, 1);
            sm2 += __shfl_xor_sync(0xffffffffu, sm2, 2);
            float inv = __fdividef(1.0f, sm2);
            a0f = e0 * inv; a1f = e1 * inv;
            if (w == 0)
                *(float2*)(out + OUT_ATTN + ((size_t)t * B_ + b) * 64 + md * 8 + n0)
                    = make_float2(a0f, a1f);
        }

        {
            float sel = (w & 1) ? a1f : a0f;
            int srcq = w >> 1;
            float4 ac = make_float4(0.f, 0.f, 0.f, 0.f);
#pragma unroll
            for (int mm = 0; mm < 8; ++mm) {
                float av = __shfl_sync(0xffffffffu, sel, mm * 4 + srcq);
                float4 v = *(const float4*)(vcs + mm * 128 + h4);
                ac.x += av * v.x; ac.y += av * v.y;
                ac.z += av * v.z; ac.w += av * v.w;
            }
            float4 hnew = make_float4(hin.x + ac.x, hin.y + ac.y,
                                      hin.z + ac.z, hin.w + ac.w);
            size_t gbase = ((size_t)t * B_ + b) * MH_ + w * 128 + h4;
            *(float4*)(out + OUT_ACM + gbase) = ac;
            *(float4*)(out + OUT_HID + gbase) = hnew;
            s = hnew;
        }
        p4 = pn;
        par ^= 1;
    }
}

extern "C" void kernel_launch(void* const* d_in, const int* in_sizes, int n_in,
                              void* d_out, int out_size) {
    const float* x     = (const float*)d_in[0];
    const float* Wp    = (const float*)d_in[1];
    const float* bp    = (const float*)d_in[2];
    const float* U     = (const float*)d_in[3];
    const float* V     = (const float*)d_in[4];
    const float* cbias = (const float*)d_in[5];
    const float* W_in  = (const float*)d_in[6];
    const float* W_Q   = (const float*)d_in[7];
    const float* W_K   = (const float*)d_in[8];
    const float* W_V   = (const float*)d_in[9];
    const float* Wo    = (const float*)d_in[10];
    const float* bo    = (const float*)d_in[11];
    float* out = (float*)d_out;

    static bool attr_done = false;
    if (!attr_done) {
        cudaFuncSetAttribute(prep_wcomb,     cudaFuncAttributeMaxDynamicSharedMemorySize, 132608);
        cudaFuncSetAttribute(gemm_in_mma,    cudaFuncAttributeMaxDynamicSharedMemorySize, GEMM_SMEM);
        cudaFuncSetAttribute(gemm_out_mma,   cudaFuncAttributeMaxDynamicSharedMemorySize, GEMM_SMEM);
        cudaFuncSetAttribute(rim_seq_kernel, cudaFuncAttributeMaxDynamicSharedMemorySize, SEQ_SMEM);
        attr_done = true;
    }

    prep_wcomb<<<M_, 256, 132608>>>(W_in, Wp);
    prep_split<<<33, 256>>>(W_in, Wo, bp, cbias);
    gemm_in_mma<<<dim3(2, S_), 256, GEMM_SMEM>>>(x, out);
    rim_seq_kernel<<<B_, 256, SEQ_SMEM>>>(U, V, W_Q, W_K, W_V, out);
    gemm_out_mma<<<dim3(2, S_), 256, GEMM_SMEM>>>(bo, out);
}

// round 16
// speedup vs baseline: 1.2869x; 1.1428x over previous
#include <cuda_runtime.h>
#include <cuda_fp16.h>
#include <cuda_bf16.h>
#include <cstdint>
#include <cstddef>

#define B_  128
#define S_  512
#define I_  128
#define H_  128
#define M_  8
#define KD_ 16
#define R_  16
#define O_  128
#define MH_ 1024

#define OUT_OUTPUTS 0ull
#define OUT_HID     8388608ull
#define OUT_AIN     75497472ull
#define OUT_ACM     142606336ull
#define OUT_ATTN    209715200ull

// ---------------- scratch ----------------
__device__ float g_P[(size_t)S_ * B_ * MH_];
__device__ float g_Wcomb[M_ * I_ * H_];
__device__ float g_biasP[MH_];
__device__ __align__(16) __nv_bfloat16 g_BinT_hi[M_ * 16384];
__device__ __align__(16) __nv_bfloat16 g_BinT_lo[M_ * 16384];
__device__ __align__(16) __nv_bfloat16 g_BpT_hi[M_ * 16384];
__device__ __align__(16) __nv_bfloat16 g_BpT_lo[M_ * 16384];
__device__ __align__(16) __nv_bfloat16 g_Wo_hi[O_ * MH_];
__device__ __align__(16) __nv_bfloat16 g_Wo_lo[O_ * MH_];

// ---------------- helpers ----------------
__device__ __forceinline__ uint32_t smem_u32(const void* p) {
    uint32_t a;
    asm("{ .reg .u64 t; cvta.to.shared.u64 t, %1; cvt.u32.u64 %0, t; }" : "=r"(a) : "l"(p));
    return a;
}
__device__ __forceinline__ uint32_t swb(int n, int k) {
    uint32_t byte = ((uint32_t)((n >> 3) + (k >> 6) * 16)) * 1024u
                  + (uint32_t)(n & 7) * 128u + (uint32_t)(k & 63) * 2u;
    return byte ^ ((byte >> 3) & 0x70u);
}
__device__ __forceinline__ uint32_t swb64(int n, int k) {
    uint32_t byte = ((uint32_t)((n >> 3) + (k >> 6) * 8)) * 1024u
                  + (uint32_t)(n & 7) * 128u + (uint32_t)(k & 63) * 2u;
    return byte ^ ((byte >> 3) & 0x70u);
}
__device__ __forceinline__ void split1(float v, uint16_t& h, uint16_t& l) {
    __nv_bfloat16 bh = __float2bfloat16(v);
    float r = v - __bfloat162float(bh);
    h = __bfloat16_as_ushort(bh);
    l = __bfloat16_as_ushort(__float2bfloat16(r));
}
__device__ __forceinline__ void ldsm4(uint32_t* r, uint32_t addr) {
    asm volatile("ldmatrix.sync.aligned.m8n8.x4.shared.b16 {%0,%1,%2,%3}, [%4];"
                 : "=r"(r[0]), "=r"(r[1]), "=r"(r[2]), "=r"(r[3]) : "r"(addr));
}
__device__ __forceinline__ void mma16816(float* c, const uint32_t* a, const uint32_t* b) {
    asm volatile("mma.sync.aligned.m16n8k16.row.col.f32.bf16.bf16.f32 "
                 "{%0,%1,%2,%3}, {%4,%5,%6,%7}, {%8,%9}, {%0,%1,%2,%3};"
                 : "+f"(c[0]), "+f"(c[1]), "+f"(c[2]), "+f"(c[3])
                 : "r"(a[0]), "r"(a[1]), "r"(a[2]), "r"(a[3]), "r"(b[0]), "r"(b[1]));
}
__device__ __forceinline__ float tanhf_fast(float x) {
    float ax = fabsf(x);
    float e = __expf(-2.0f * ax);
    float r = __fdividef(1.0f - e, 1.0f + e);
    return copysignf(r, x);
}

#define A_HI 0
#define A_LO 16384
#define B_HI 32768
#define B_LO 65536
#define GEMM_SMEM 98304

// ---------------------------------------------------------------------------
// prep 0
// ---------------------------------------------------------------------------
__global__ void __launch_bounds__(256) prep_wcomb(const float* __restrict__ W_in,
                                                  const float* __restrict__ Wp) {
    extern __shared__ float s0[];
    float* Wins = s0;
    float* Wps  = s0 + 16384;
    int m = blockIdx.x, tid = threadIdx.x;
    const float* wi = W_in + m * 16384;
    const float* wp = Wp   + m * 16384;
    for (int i = tid; i < 16384; i += 256) {
        Wins[i] = wi[i];
        Wps[(i >> 7) * 129 + (i & 127)] = wp[i];
    }
    __syncthreads();
    for (int idx = tid; idx < 16384; idx += 256) {
        int j = idx >> 7, o = idx & 127;
        const float* a = Wins + j * 128;
        const float* b = Wps + o * 129;
        float acc = 0.f;
#pragma unroll 16
        for (int i = 0; i < 128; ++i) acc += a[i] * b[i];
        g_Wcomb[m * 16384 + idx] = acc;
    }
}

// ---------------------------------------------------------------------------
// prep 1
// ---------------------------------------------------------------------------
__global__ void __launch_bounds__(256) prep_split(const float* __restrict__ W_in,
                                                  const float* __restrict__ Wo,
                                                  const float* __restrict__ bp,
                                                  const float* __restrict__ cbias) {
    int b = blockIdx.x, tid = threadIdx.x;
    if (b < 8) {
        int m = b;
        for (int idx = tid; idx < 16384; idx += 256) {
            int h = idx >> 7, i = idx & 127;
            uint16_t hi, lo;
            split1(W_in[m * 16384 + i * 128 + h], hi, lo);
            g_BinT_hi[m * 16384 + idx] = __ushort_as_bfloat16(hi);
            g_BinT_lo[m * 16384 + idx] = __ushort_as_bfloat16(lo);
        }
    } else if (b < 16) {
        int m = b - 8;
        for (int idx = tid; idx < 16384; idx += 256) {
            int o = idx >> 7, i = idx & 127;
            uint16_t hi, lo;
            split1(g_Wcomb[m * 16384 + i * 128 + o], hi, lo);
            g_BpT_hi[m * 16384 + idx] = __ushort_as_bfloat16(hi);
            g_BpT_lo[m * 16384 + idx] = __ushort_as_bfloat16(lo);
        }
    } else if (b < 32) {
        int s = b - 16;
        for (int idx = tid; idx < 8192; idx += 256) {
            int g = s * 8192 + idx;
            uint16_t hi, lo;
            split1(Wo[g], hi, lo);
            g_Wo_hi[g] = __ushort_as_bfloat16(hi);
            g_Wo_lo[g] = __ushort_as_bfloat16(lo);
        }
    } else {
        for (int idx = tid; idx < MH_; idx += 256) g_biasP[idx] = bp[idx] + cbias[idx];
    }
}

// ---------------------------------------------------------------------------
// shared GEMM body (batch-split 64 rows). isP selects weights + destination.
// ---------------------------------------------------------------------------
__device__ __forceinline__ void gemm_xw_body(const float* __restrict__ x,
                                             float* __restrict__ out,
                                             char* smc, bool isP) {
    uint32_t sb = smem_u32(smc);
    int tid = threadIdx.x, w = tid >> 5, lane = tid & 31;
    int t = blockIdx.y, half = blockIdx.x;

    {
        int rb = tid >> 2, qq = (tid & 3) * 32;
        const float4* xr = (const float4*)(x + ((size_t)(half * 64 + rb) * S_ + t) * I_ + qq);
#pragma unroll
        for (int q = 0; q < 8; ++q) {
            float4 v = xr[q];
            int k0 = qq + q * 4;
            uint16_t h0, h1, h2, h3, l0, l1, l2, l3;
            split1(v.x, h0, l0); split1(v.y, h1, l1);
            split1(v.z, h2, l2); split1(v.w, h3, l3);
            uint2 hv = make_uint2((uint32_t)h0 | ((uint32_t)h1 << 16),
                                  (uint32_t)h2 | ((uint32_t)h3 << 16));
            uint2 lv = make_uint2((uint32_t)l0 | ((uint32_t)l1 << 16),
                                  (uint32_t)l2 | ((uint32_t)l3 << 16));
            uint32_t off = swb64(rb, k0);
            *(uint2*)(smc + A_HI + off) = hv;
            *(uint2*)(smc + A_LO + off) = lv;
        }
    }

    int lq = lane >> 3, ll = lane & 7;
    int rt = w >> 1, ch = w & 1;
    int a_row = rt * 16 + ll + (lq & 1) * 8;
    int a_kadd = (lq >> 1) * 8;
    int b_rc = (lq >> 1) * 8 + ll;
    int b_kadd = (lq & 1) * 8;
    int c_row = rt * 16 + (lane >> 2);
    int c_col = (lane & 3) * 2;

    for (int m = 0; m < 8; ++m) {
        const __nv_bfloat16* gh = (isP ? g_BpT_hi : g_BinT_hi) + m * 16384;
        const __nv_bfloat16* gl = (isP ? g_BpT_lo : g_BinT_lo) + m * 16384;
#pragma unroll
        for (int q = 0; q < 8; ++q) {
            int u = tid + q * 256;
            int n = u >> 4, k0 = (u & 15) * 8;
            uint4 vh = ((const uint4*)gh)[u];
            uint4 vl = ((const uint4*)gl)[u];
            uint32_t off = swb(n, k0);
            *(uint4*)(smc + B_HI + off) = vh;
            *(uint4*)(smc + B_LO + off) = vl;
        }
        __syncthreads();

        float c[8][4];
#pragma unroll
        for (int i = 0; i < 8; ++i)
#pragma unroll
            for (int j = 0; j < 4; ++j) c[i][j] = 0.f;

        for (int ks = 0; ks < 8; ++ks) {
            int k0 = ks * 16;
            uint32_t ah[4], al[4];
            uint32_t aoff = swb64(a_row, k0 + a_kadd);
            ldsm4(ah, sb + A_HI + aoff);
            ldsm4(al, sb + A_LO + aoff);
#pragma unroll
            for (int np = 0; np < 4; ++np) {
                uint32_t bh[4], bl[4];
                uint32_t boff = swb(ch * 64 + np * 16 + b_rc, k0 + b_kadd);
                ldsm4(bh, sb + B_HI + boff);
                ldsm4(bl, sb + B_LO + boff);
                mma16816(c[2 * np],     ah, bh);
                mma16816(c[2 * np],     ah, bl);
                mma16816(c[2 * np],     al, bh);
                mma16816(c[2 * np + 1], ah, bh + 2);
                mma16816(c[2 * np + 1], ah, bl + 2);
                mma16816(c[2 * np + 1], al, bh + 2);
            }
        }

        int r0 = half * 64 + c_row;
        if (!isP) {
            float* d0 = out + OUT_AIN + ((size_t)t * B_ + r0) * MH_ + m * H_ + ch * 64;
            float* d1 = out + OUT_AIN + ((size_t)t * B_ + r0 + 8) * MH_ + m * H_ + ch * 64;
#pragma unroll
            for (int nt = 0; nt < 8; ++nt) {
                int col = nt * 8 + c_col;
                *(float2*)(d0 + col) = make_float2(c[nt][0], c[nt][1]);
                *(float2*)(d1 + col) = make_float2(c[nt][2], c[nt][3]);
            }
        } else {
            float* d0 = g_P + ((size_t)t * B_ + r0) * MH_ + m * H_ + ch * 64;
            float* d1 = g_P + ((size_t)t * B_ + r0 + 8) * MH_ + m * H_ + ch * 64;
#pragma unroll
            for (int nt = 0; nt < 8; ++nt) {
                int col = nt * 8 + c_col;
                float2 bi = *(const float2*)(g_biasP + m * H_ + ch * 64 + col);
                *(float2*)(d0 + col) = make_float2(c[nt][0] + bi.x, c[nt][1] + bi.y);
                *(float2*)(d1 + col) = make_float2(c[nt][2] + bi.x, c[nt][3] + bi.y);
            }
        }
        __syncthreads();
    }
}

__global__ void __launch_bounds__(256)
gemm_P_mma(const float* __restrict__ x, float* __restrict__ out) {
    extern __shared__ char smc[];
    gemm_xw_body(x, out, smc, true);
}
__global__ void __launch_bounds__(256)
gemm_ain_mma(const float* __restrict__ x, float* __restrict__ out) {
    extern __shared__ char smc[];
    gemm_xw_body(x, out, smc, false);
}

// ---------------------------------------------------------------------------
// GEMM C (mma.sync bf16-split), batch-split (unchanged)
// ---------------------------------------------------------------------------
__global__ void __launch_bounds__(256)
gemm_out_mma(const float* __restrict__ bo, float* __restrict__ out) {
    extern __shared__ char smc[];
    uint32_t sb = smem_u32(smc);
    int tid = threadIdx.x, w = tid >> 5, lane = tid & 31;
    int t = blockIdx.y, half = blockIdx.x;
    const float* hid = out + OUT_HID + (size_t)t * B_ * MH_ + (size_t)half * 64 * MH_;

    int lq = lane >> 3, ll = lane & 7;
    int rt = w >> 1, ch = w & 1;
    int a_row = rt * 16 + ll + (lq & 1) * 8;
    int a_kadd = (lq >> 1) * 8;
    int b_rc = (lq >> 1) * 8 + ll;
    int b_kadd = (lq & 1) * 8;
    int c_row = rt * 16 + (lane >> 2);
    int c_col = (lane & 3) * 2;

    float c[8][4];
#pragma unroll
    for (int i = 0; i < 8; ++i)
#pragma unroll
        for (int j = 0; j < 4; ++j) c[i][j] = 0.f;

    for (int kc = 0; kc < 8; ++kc) {
        {
            int rb = tid >> 2, qq = (tid & 3) * 32;
            const float4* ar = (const float4*)(hid + (size_t)rb * MH_ + kc * 128 + qq);
#pragma unroll
            for (int q = 0; q < 8; ++q) {
                float4 v = ar[q];
                int k0 = qq + q * 4;
                uint16_t h0, h1, h2, h3, l0, l1, l2, l3;
                split1(v.x, h0, l0); split1(v.y, h1, l1);
                split1(v.z, h2, l2); split1(v.w, h3, l3);
                uint2 hv = make_uint2((uint32_t)h0 | ((uint32_t)h1 << 16),
                                      (uint32_t)h2 | ((uint32_t)h3 << 16));
                uint2 lv = make_uint2((uint32_t)l0 | ((uint32_t)l1 << 16),
                                      (uint32_t)l2 | ((uint32_t)l3 << 16));
                uint32_t off = swb64(rb, k0);
                *(uint2*)(smc + A_HI + off) = hv;
                *(uint2*)(smc + A_LO + off) = lv;
            }
        }
#pragma unroll
        for (int q = 0; q < 8; ++q) {
            int u = tid + q * 256;
            int n = u >> 4, k0 = (u & 15) * 8;
            uint4 vh = *(const uint4*)(g_Wo_hi + (size_t)n * MH_ + kc * 128 + k0);
            uint4 vl = *(const uint4*)(g_Wo_lo + (size_t)n * MH_ + kc * 128 + k0);
            uint32_t off = swb(n, k0);
            *(uint4*)(smc + B_HI + off) = vh;
            *(uint4*)(smc + B_LO + off) = vl;
        }
        __syncthreads();

        for (int ks = 0; ks < 8; ++ks) {
            int k0 = ks * 16;
            uint32_t ah[4], al[4];
            uint32_t aoff = swb64(a_row, k0 + a_kadd);
            ldsm4(ah, sb + A_HI + aoff);
            ldsm4(al, sb + A_LO + aoff);
#pragma unroll
            for (int np = 0; np < 4; ++np) {
                uint32_t bh[4], bl[4];
                uint32_t boff = swb(ch * 64 + np * 16 + b_rc, k0 + b_kadd);
                ldsm4(bh, sb + B_HI + boff);
                ldsm4(bl, sb + B_LO + boff);
                mma16816(c[2 * np],     ah, bh);
                mma16816(c[2 * np],     ah, bl);
                mma16816(c[2 * np],     al, bh);
                mma16816(c[2 * np + 1], ah, bh + 2);
                mma16816(c[2 * np + 1], ah, bl + 2);
                mma16816(c[2 * np + 1], al, bh + 2);
            }
        }
        __syncthreads();
    }

    int r0 = half * 64 + c_row;
    float* d0 = out + OUT_OUTPUTS + ((size_t)r0 * S_ + t) * O_ + ch * 64;
    float* d1 = out + OUT_OUTPUTS + ((size_t)(r0 + 8) * S_ + t) * O_ + ch * 64;
#pragma unroll
    for (int nt = 0; nt < 8; ++nt) {
        int col = nt * 8 + c_col;
        float2 bi = *(const float2*)(bo + ch * 64 + col);
        *(float2*)(d0 + col) = make_float2(c[nt][0] + bi.x, c[nt][1] + bi.y);
        *(float2*)(d1 + col) = make_float2(c[nt][2] + bi.x, c[nt][3] + bi.y);
    }
}

// ---------------------------------------------------------------------------
// Kernel B: sequential recurrence — padded KQ (20-float vectors, bank-clean)
// smem: half Wt[256*136] | uint his_h[512] | float vcs[2][1024] | KQ[2][32*20]
// ---------------------------------------------------------------------------
#define WT_HALFS (256 * 136)
#define KQ_STRIDE 20
#define KQ_BUF (32 * KQ_STRIDE)
#define SEQ_SMEM (WT_HALFS * 2 + 512 * 4 + 2048 * 4 + 2 * KQ_BUF * 4)

__global__ void __launch_bounds__(256) rim_seq_kernel(const float* __restrict__ U,
                                                      const float* __restrict__ V,
                                                      const float* __restrict__ WQ,
                                                      const float* __restrict__ WK,
                                                      const float* __restrict__ WV,
                                                      float* __restrict__ out) {
    extern __shared__ char smc[];
    __half* Wt = (__half*)smc;
    uint32_t* his_h = (uint32_t*)(Wt + WT_HALFS);
    float* vcsB = (float*)(his_h + 512);
    float* KQB = vcsB + 2048;

    int tid = threadIdx.x, b = blockIdx.x;
    int w = tid >> 5, lane = tid & 31;
    int h4 = lane * 4;

    for (int i = tid; i < 16384; i += 256) {
        int m = i >> 11, h = (i >> 4) & 127, k = i & 15;
        Wt[(m * 32 + k) * 136 + h] = __float2half(WK[i]);
        Wt[(m * 32 + 16 + k) * 136 + h] = __float2half(WQ[i]);
    }

    float Ur[4][16];
#pragma unroll
    for (int j = 0; j < 4; ++j) {
        const float4* ur = (const float4*)(U + w * 2048 + (h4 + j) * 16);
#pragma unroll
        for (int q = 0; q < 4; ++q) {
            float4 v = ur[q];
            Ur[j][q * 4 + 0] = v.x; Ur[j][q * 4 + 1] = v.y;
            Ur[j][q * 4 + 2] = v.z; Ur[j][q * 4 + 3] = v.w;
        }
    }
    float4 Vr[16];
#pragma unroll
    for (int r = 0; r < 16; ++r)
        Vr[r] = *(const float4*)(V + w * 2048 + r * 128 + h4);

    float4 wv4;
    wv4.x = WV[w * 16384 + (h4 + 0) * 128 + (h4 + 0)];
    wv4.y = WV[w * 16384 + (h4 + 1) * 128 + (h4 + 1)];
    wv4.z = WV[w * 16384 + (h4 + 2) * 128 + (h4 + 2)];
    wv4.w = WV[w * 16384 + (h4 + 3) * 128 + (h4 + 3)];

    float4 s = make_float4(0.f, 0.f, 0.f, 0.f);
    __syncthreads();

    const __half* Wr = Wt + (w * 32 + lane) * 136;
    const uint4* Hm4 = (const uint4*)(his_h + w * 64);
    int md = lane >> 2, n0 = (lane & 3) * 2;
    int vidx = (lane < 16) ? w : (16 + w);

    float4 p4 = *(const float4*)(g_P + (size_t)b * MH_ + w * 128 + h4);
    int par = 0;

    for (int t = 0; t < S_; ++t) {
        float* vcs = vcsB + par * 1024;
        float* KQ = KQB + par * KQ_BUF;

        float part[16];
#pragma unroll
        for (int r = 0; r < 16; ++r)
            part[r] = s.x * Ur[0][r] + s.y * Ur[1][r] + s.z * Ur[2][r] + s.w * Ur[3][r];
        {
            bool sel = (lane & 16) != 0;
#pragma unroll
            for (int j = 0; j < 8; ++j) {
                float keep = sel ? part[8 + j] : part[j];
                float send = sel ? part[j] : part[8 + j];
                part[j] = keep + __shfl_xor_sync(0xffffffffu, send, 16);
            }
        }
        {
            bool sel = (lane & 8) != 0;
#pragma unroll
            for (int j = 0; j < 4; ++j) {
                float keep = sel ? part[4 + j] : part[j];
                float send = sel ? part[j] : part[4 + j];
                part[j] = keep + __shfl_xor_sync(0xffffffffu, send, 8);
            }
        }
        {
            bool sel = (lane & 4) != 0;
#pragma unroll
            for (int j = 0; j < 2; ++j) {
                float keep = sel ? part[2 + j] : part[j];
                float send = sel ? part[j] : part[2 + j];
                part[j] = keep + __shfl_xor_sync(0xffffffffu, send, 4);
            }
        }
        {
            bool sel = (lane & 2) != 0;
            float keep = sel ? part[1] : part[0];
            float send = sel ? part[0] : part[1];
            part[0] = keep + __shfl_xor_sync(0xffffffffu, send, 2);
        }
        float tsum = part[0] + __shfl_xor_sync(0xffffffffu, part[0], 1);

        float4 hin;
        {
            float4 z = p4;
#pragma unroll
            for (int r = 0; r < 16; ++r) {
                float tr = __shfl_sync(0xffffffffu, tsum, r << 1);
                z.x += tr * Vr[r].x; z.y += tr * Vr[r].y;
                z.z += tr * Vr[r].z; z.w += tr * Vr[r].w;
            }
            hin.x = tanhf_fast(z.x); hin.y = tanhf_fast(z.y);
            hin.z = tanhf_fast(z.z); hin.w = tanhf_fast(z.w);
            __half2 p01 = __floats2half2_rn(hin.x, hin.y);
            __half2 p23 = __floats2half2_rn(hin.z, hin.w);
            *(uint2*)(his_h + w * 64 + lane * 2) =
                make_uint2(*(uint32_t*)&p01, *(uint32_t*)&p23);
            *(float4*)(vcs + w * 128 + h4) = make_float4(hin.x * wv4.x, hin.y * wv4.y,
                                                         hin.z * wv4.z, hin.w * wv4.w);
        }
        __syncwarp();

        {
            __half2 a0 = __float2half2_rn(0.f), a1 = a0, a2 = a0, a3 = a0;
#pragma unroll
            for (int j = 0; j < 16; ++j) {
                uint4 w8 = *(const uint4*)(Wr + j * 8);
                uint4 h8 = Hm4[j];
                a0 = __hfma2(*(__half2*)&w8.x, *(__half2*)&h8.x, a0);
                a1 = __hfma2(*(__half2*)&w8.y, *(__half2*)&h8.y, a1);
                a2 = __hfma2(*(__half2*)&w8.z, *(__half2*)&h8.z, a2);
                a3 = __hfma2(*(__half2*)&w8.w, *(__half2*)&h8.w, a3);
            }
            __half2 s01 = __hadd2(a0, a1);
            __half2 s23 = __hadd2(a2, a3);
            __half2 ss = __hadd2(s01, s23);
            float acc = __half2float(__low2half(ss)) + __half2float(__high2half(ss));
            KQ[vidx * KQ_STRIDE + (lane & 15)] = acc;
        }
        __syncthreads();

        float4 pn;
        {
            int tn = (t + 1) & (S_ - 1);
            pn = *(const float4*)(g_P + ((size_t)tn * B_ + b) * MH_ + w * 128 + h4);
        }

        float a0f, a1f;
        {
            const float* qrow = KQ + (16 + md) * KQ_STRIDE;
            const float* k0r = KQ + n0 * KQ_STRIDE;
            const float* k1r = KQ + (n0 + 1) * KQ_STRIDE;
            float lg0 = 0.f, lg1 = 0.f;
#pragma unroll
            for (int k4 = 0; k4 < 16; k4 += 4) {
                float4 q = *(const float4*)(qrow + k4);
                float4 ka = *(const float4*)(k0r + k4);
                float4 kb = *(const float4*)(k1r + k4);
                lg0 += q.x * ka.x + q.y * ka.y + q.z * ka.z + q.w * ka.w;
                lg1 += q.x * kb.x + q.y * kb.y + q.z * kb.z + q.w * kb.w;
            }
            lg0 *= 0.25f; lg1 *= 0.25f;
            float mx = fmaxf(lg0, lg1);
            mx = fmaxf(mx, __shfl_xor_sync(0xffffffffu, mx, 1));
            mx = fmaxf(mx, __shfl_xor_sync(0xffffffffu, mx, 2));
            float e0 = __expf(lg0 - mx), e1 = __expf(lg1 - mx);
            float sm2 = e0 + e1;
            sm2 += __shfl_xor_sync(0xffffffffu, sm2, 1);
            sm2 += __shfl_xor_sync(0xffffffffu, sm2, 2);
            float inv = __fdividef(1.0f, sm2);
            a0f = e0 * inv; a1f = e1 * inv;
            if (w == 0)
                *(float2*)(out + OUT_ATTN + ((size_t)t * B_ + b) * 64 + md * 8 + n0)
                    = make_float2(a0f, a1f);
        }

        {
            float sel = (w & 1) ? a1f : a0f;
            int srcq = w >> 1;
            float4 ac = make_float4(0.f, 0.f, 0.f, 0.f);
#pragma unroll
            for (int mm = 0; mm < 8; ++mm) {
                float av = __shfl_sync(0xffffffffu, sel, mm * 4 + srcq);
                float4 v = *(const float4*)(vcs + mm * 128 + h4);
                ac.x += av * v.x; ac.y += av * v.y;
                ac.z += av * v.z; ac.w += av * v.w;
            }
            float4 hnew = make_float4(hin.x + ac.x, hin.y + ac.y,
                                      hin.z + ac.z, hin.w + ac.w);
            size_t gbase = ((size_t)t * B_ + b) * MH_ + w * 128 + h4;
            *(float4*)(out + OUT_ACM + gbase) = ac;
            *(float4*)(out + OUT_HID + gbase) = hnew;
            s = hnew;
        }
        p4 = pn;
        par ^= 1;
    }
}

extern "C" void kernel_launch(void* const* d_in, const int* in_sizes, int n_in,
                              void* d_out, int out_size) {
    const float* x     = (const float*)d_in[0];
    const float* Wp    = (const float*)d_in[1];
    const float* bp    = (const float*)d_in[2];
    const float* U     = (const float*)d_in[3];
    const float* V     = (const float*)d_in[4];
    const float* cbias = (const float*)d_in[5];
    const float* W_in  = (const float*)d_in[6];
    const float* W_Q   = (const float*)d_in[7];
    const float* W_K   = (const float*)d_in[8];
    const float* W_V   = (const float*)d_in[9];
    const float* Wo    = (const float*)d_in[10];
    const float* bo    = (const float*)d_in[11];
    float* out = (float*)d_out;

    static cudaStream_t s1 = nullptr;
    static cudaEvent_t evFork = nullptr, evJoin = nullptr;
    static bool attr_done = false;
    if (!attr_done) {
        cudaFuncSetAttribute(prep_wcomb,     cudaFuncAttributeMaxDynamicSharedMemorySize, 132608);
        cudaFuncSetAttribute(gemm_P_mma,     cudaFuncAttributeMaxDynamicSharedMemorySize, GEMM_SMEM);
        cudaFuncSetAttribute(gemm_ain_mma,   cudaFuncAttributeMaxDynamicSharedMemorySize, GEMM_SMEM);
        cudaFuncSetAttribute(gemm_out_mma,   cudaFuncAttributeMaxDynamicSharedMemorySize, GEMM_SMEM);
        cudaFuncSetAttribute(rim_seq_kernel, cudaFuncAttributeMaxDynamicSharedMemorySize, SEQ_SMEM);
        int lo, hi;
        cudaDeviceGetStreamPriorityRange(&lo, &hi);
        cudaStreamCreateWithPriority(&s1, cudaStreamNonBlocking, lo);   // LOW priority
        cudaEventCreateWithFlags(&evFork, cudaEventDisableTiming);
        cudaEventCreateWithFlags(&evJoin, cudaEventDisableTiming);
        attr_done = true;
    }

    prep_wcomb<<<M_, 256, 132608>>>(W_in, Wp);
    prep_split<<<33, 256>>>(W_in, Wo, bp, cbias);
    gemm_P_mma<<<dim3(2, S_), 256, GEMM_SMEM>>>(x, out);

    // fork: A_in GEMM on low-priority side stream, overlapping with seq
    cudaEventRecord(evFork, 0);
    cudaStreamWaitEvent(s1, evFork, 0);
    gemm_ain_mma<<<dim3(2, S_), 256, GEMM_SMEM, s1>>>(x, out);
    cudaEventRecord(evJoin, s1);

    rim_seq_kernel<<<B_, 256, SEQ_SMEM>>>(U, V, W_Q, W_K, W_V, out);
    gemm_out_mma<<<dim3(2, S_), 256, GEMM_SMEM>>>(bo, out);

    // join before harness validates
    cudaStreamWaitEvent(0, evJoin, 0);
}